// round 2
// baseline (speedup 1.0000x reference)
#include <cuda_runtime.h>
#include <math.h>

#define T_TOKENS 4096
#define DDIM 768
#define HDIM 2688
#define NEXP 8
#define TOPK 2
#define Z_COEFF 1e-5f

// ---------------- device scratch (static, no allocations) ----------------
__device__ int   g_cnt[NEXP];
__device__ int   g_tok[NEXP][T_TOKENS];
__device__ float g_wt[NEXP][T_TOKENS];
__device__ float g_zsum;
// activation buffer: [E][T][H] fp32, fixed stride per expert (worst case)
__device__ float g_act[(size_t)NEXP * T_TOKENS * HDIM];

// ---------------- init: zero output + counters ----------------
__global__ void k_init(float* __restrict__ out, int n) {
    int i = blockIdx.x * blockDim.x + threadIdx.x;
    if (i < n) out[i] = 0.0f;
    if (blockIdx.x == 0) {
        if (threadIdx.x < NEXP) g_cnt[threadIdx.x] = 0;
        if (threadIdx.x == 0) g_zsum = 0.0f;
    }
}

// ---------------- router ----------------
// one block per token; 8 warps, warp e computes logit for expert e
__global__ void k_router(const float* __restrict__ x,
                         const float* __restrict__ gw,
                         const float* __restrict__ bias) {
    const int t = blockIdx.x;
    __shared__ float s_logits[NEXP];
    const int warp = threadIdx.x >> 5;
    const int lane = threadIdx.x & 31;
    const float* xr = x + (size_t)t * DDIM;
    const float* w = gw + (size_t)warp * DDIM;
    float s = 0.0f;
    for (int d = lane; d < DDIM; d += 32) s = fmaf(xr[d], w[d], s);
    #pragma unroll
    for (int o = 16; o; o >>= 1) s += __shfl_xor_sync(0xffffffffu, s, o);
    if (lane == 0) s_logits[warp] = s;
    __syncthreads();
    if (threadIdx.x == 0) {
        float l[NEXP];
        #pragma unroll
        for (int e = 0; e < NEXP; e++) l[e] = s_logits[e];
        // top-2 on biased logits (stable: earlier index wins ties)
        int i0 = 0, i1 = -1;
        float b0 = -1e30f, b1 = -1e30f;
        #pragma unroll
        for (int e = 0; e < NEXP; e++) {
            float v = l[e] + bias[e];
            if (v > b0) { b1 = b0; i1 = i0; b0 = v; i0 = e; }
            else if (v > b1) { b1 = v; i1 = e; }
        }
        // softmax over UNbiased selected logits
        float l0 = l[i0], l1 = l[i1];
        float m = fmaxf(l0, l1);
        float e0 = expf(l0 - m), e1 = expf(l1 - m);
        float inv = 1.0f / (e0 + e1);
        float w0 = e0 * inv, w1 = e1 * inv;
        // z-loss: logsumexp^2
        float mx = l[0];
        #pragma unroll
        for (int e = 1; e < NEXP; e++) mx = fmaxf(mx, l[e]);
        float se = 0.0f;
        #pragma unroll
        for (int e = 0; e < NEXP; e++) se += expf(l[e] - mx);
        float lse = mx + logf(se);
        atomicAdd(&g_zsum, lse * lse);
        int p0 = atomicAdd(&g_cnt[i0], 1);
        g_tok[i0][p0] = t; g_wt[i0][p0] = w0;
        int p1 = atomicAdd(&g_cnt[i1], 1);
        g_tok[i1][p1] = t; g_wt[i1][p1] = w1;
    }
}

// ---------------- phase 1: act = silu(x Wg) * (x Wu), grouped per expert ----------------
// tile 64(M) x 64(N) x 16(K), 256 threads, 4x4 micro-tile, two B matrices
__global__ __launch_bounds__(256)
void k_gu(const float* __restrict__ x,
          const float* __restrict__ w_gate,
          const float* __restrict__ w_up) {
    const int e = blockIdx.z;
    const int cnt = g_cnt[e];
    const int m0 = blockIdx.y * 64;
    if (m0 >= cnt) return;
    const int n0 = blockIdx.x * 64;

    __shared__ float sx[16][64];
    __shared__ float sg[16][64];
    __shared__ float su[16][64];

    const int tid = threadIdx.x;
    const int tx = tid & 15;       // micro-tile col group
    const int ty = tid >> 4;       // micro-tile row group
    // A-tile load mapping: one float4 per thread over [64 rows][16 cols]
    const int lrow = tid >> 2;           // 0..63
    const int lcol = (tid & 3) << 2;     // 0,4,8,12
    const int slot = m0 + lrow;
    const bool avalid = slot < cnt;
    const int tok = avalid ? g_tok[e][slot] : 0;
    const float* xrow = x + (size_t)tok * DDIM;
    // B-tile load mapping: one float4 per thread over [16 rows][64 cols]
    const int bk = tid >> 4;             // 0..15
    const int bn = (tid & 15) << 2;      // 0..60
    const float* wg = w_gate + (size_t)e * DDIM * HDIM;
    const float* wu = w_up   + (size_t)e * DDIM * HDIM;

    float ag[4][4] = {};
    float au[4][4] = {};

    for (int d0 = 0; d0 < DDIM; d0 += 16) {
        float4 xa = avalid ? *(const float4*)(xrow + d0 + lcol)
                           : make_float4(0.f, 0.f, 0.f, 0.f);
        sx[lcol + 0][lrow] = xa.x;
        sx[lcol + 1][lrow] = xa.y;
        sx[lcol + 2][lrow] = xa.z;
        sx[lcol + 3][lrow] = xa.w;
        *(float4*)&sg[bk][bn] = *(const float4*)(wg + (size_t)(d0 + bk) * HDIM + n0 + bn);
        *(float4*)&su[bk][bn] = *(const float4*)(wu + (size_t)(d0 + bk) * HDIM + n0 + bn);
        __syncthreads();
        #pragma unroll
        for (int kk = 0; kk < 16; kk++) {
            float4 av = *(const float4*)&sx[kk][ty << 2];
            float4 bg = *(const float4*)&sg[kk][tx << 2];
            float4 bu = *(const float4*)&su[kk][tx << 2];
            float a[4]  = {av.x, av.y, av.z, av.w};
            float vg[4] = {bg.x, bg.y, bg.z, bg.w};
            float vu[4] = {bu.x, bu.y, bu.z, bu.w};
            #pragma unroll
            for (int i = 0; i < 4; i++)
                #pragma unroll
                for (int j = 0; j < 4; j++) {
                    ag[i][j] = fmaf(a[i], vg[j], ag[i][j]);
                    au[i][j] = fmaf(a[i], vu[j], au[i][j]);
                }
        }
        __syncthreads();
    }

    const int hbase = n0 + (tx << 2);
    #pragma unroll
    for (int i = 0; i < 4; i++) {
        int s2 = m0 + (ty << 2) + i;
        if (s2 < cnt) {
            float* dst = g_act + ((size_t)e * T_TOKENS + s2) * HDIM + hbase;
            float4 v;
            float g0 = ag[i][0], g1 = ag[i][1], g2 = ag[i][2], g3 = ag[i][3];
            v.x = (g0 / (1.0f + __expf(-g0))) * au[i][0];
            v.y = (g1 / (1.0f + __expf(-g1))) * au[i][1];
            v.z = (g2 / (1.0f + __expf(-g2))) * au[i][2];
            v.w = (g3 / (1.0f + __expf(-g3))) * au[i][3];
            *(float4*)dst = v;
        }
    }
}

// ---------------- phase 2: out += weight * (act Wd), grouped per expert ----------------
__global__ __launch_bounds__(256)
void k_down(const float* __restrict__ w_down, float* __restrict__ out) {
    const int e = blockIdx.z;
    const int cnt = g_cnt[e];
    const int m0 = blockIdx.y * 64;
    if (m0 >= cnt) return;
    const int n0 = blockIdx.x * 64;   // over D (12 tiles)

    __shared__ float sa[16][64];
    __shared__ float sb[16][64];

    const int tid = threadIdx.x;
    const int tx = tid & 15;
    const int ty = tid >> 4;
    const int lrow = tid >> 2;
    const int lcol = (tid & 3) << 2;
    const int slot = m0 + lrow;
    const bool avalid = slot < cnt;
    const float* arow = g_act + ((size_t)e * T_TOKENS + (avalid ? slot : 0)) * HDIM;
    const int bk = tid >> 4;
    const int bn = (tid & 15) << 2;
    const float* wd = w_down + (size_t)e * HDIM * DDIM;

    float acc[4][4] = {};

    for (int h0 = 0; h0 < HDIM; h0 += 16) {
        float4 xa = avalid ? *(const float4*)(arow + h0 + lcol)
                           : make_float4(0.f, 0.f, 0.f, 0.f);
        sa[lcol + 0][lrow] = xa.x;
        sa[lcol + 1][lrow] = xa.y;
        sa[lcol + 2][lrow] = xa.z;
        sa[lcol + 3][lrow] = xa.w;
        *(float4*)&sb[bk][bn] = *(const float4*)(wd + (size_t)(h0 + bk) * DDIM + n0 + bn);
        __syncthreads();
        #pragma unroll
        for (int kk = 0; kk < 16; kk++) {
            float4 av = *(const float4*)&sa[kk][ty << 2];
            float4 bv = *(const float4*)&sb[kk][tx << 2];
            float a[4] = {av.x, av.y, av.z, av.w};
            float b[4] = {bv.x, bv.y, bv.z, bv.w};
            #pragma unroll
            for (int i = 0; i < 4; i++)
                #pragma unroll
                for (int j = 0; j < 4; j++)
                    acc[i][j] = fmaf(a[i], b[j], acc[i][j]);
        }
        __syncthreads();
    }

    const int dbase = n0 + (tx << 2);
    #pragma unroll
    for (int i = 0; i < 4; i++) {
        int s2 = m0 + (ty << 2) + i;
        if (s2 < cnt) {
            int t = g_tok[e][s2];
            float w = g_wt[e][s2];
            float* dst = out + (size_t)t * DDIM + dbase;
            #pragma unroll
            for (int j = 0; j < 4; j++)
                atomicAdd(&dst[j], w * acc[i][j]);
        }
    }
}

// ---------------- z-loss finalize ----------------
__global__ void k_zloss(float* __restrict__ zout) {
    zout[0] = Z_COEFF * g_zsum / (float)T_TOKENS;
}

extern "C" void kernel_launch(void* const* d_in, const int* in_sizes, int n_in,
                              void* d_out, int out_size) {
    const float* x           = (const float*)d_in[0];
    const float* gate_w      = (const float*)d_in[1];
    const float* expert_bias = (const float*)d_in[2];
    const float* w_gate      = (const float*)d_in[3];
    const float* w_up        = (const float*)d_in[4];
    const float* w_down      = (const float*)d_in[5];
    float* out = (float*)d_out;

    const int n_main = T_TOKENS * DDIM;

    k_init<<<(out_size + 255) / 256, 256>>>(out, out_size);
    k_router<<<T_TOKENS, 256>>>(x, gate_w, expert_bias);
    k_gu<<<dim3(HDIM / 64, T_TOKENS / 64, NEXP), 256>>>(x, w_gate, w_up);
    k_down<<<dim3(DDIM / 64, T_TOKENS / 64, NEXP), 256>>>(w_down, out);
    if (out_size > n_main) {
        k_zloss<<<1, 1>>>(out + n_main);
    }
}

// round 3
// speedup vs baseline: 1.1466x; 1.1466x over previous
#include <cuda_runtime.h>
#include <math.h>

#define T_TOKENS 4096
#define DDIM 768
#define HDIM 2688
#define NEXP 8
#define Z_COEFF 1e-5f

typedef unsigned long long u64;

// ---------------- packed f32x2 helpers (Blackwell FFMA2) ----------------
__device__ __forceinline__ u64 pack2(float lo, float hi) {
    u64 r;
    asm("mov.b64 %0, {%1, %2};" : "=l"(r) : "f"(lo), "f"(hi));
    return r;
}
__device__ __forceinline__ u64 dup2(float v) {
    u64 r;
    asm("mov.b64 %0, {%1, %1};" : "=l"(r) : "f"(v));
    return r;
}
__device__ __forceinline__ void fma2(u64& acc, u64 a, u64 b) {
    asm("fma.rn.f32x2 %0, %1, %2, %0;" : "+l"(acc) : "l"(a), "l"(b));
}
__device__ __forceinline__ void unpack2(u64 v, float& lo, float& hi) {
    asm("mov.b64 {%0, %1}, %2;" : "=f"(lo), "=f"(hi) : "l"(v));
}

// ---------------- device scratch (static, no allocations) ----------------
__device__ int   g_cnt[NEXP];
__device__ int   g_tok[NEXP][T_TOKENS];
__device__ float g_wt[NEXP][T_TOKENS];
__device__ float g_zsum;
__device__ float g_act[(size_t)NEXP * T_TOKENS * HDIM];

// ---------------- init ----------------
__global__ void k_init(float* __restrict__ out, int n) {
    int i = blockIdx.x * blockDim.x + threadIdx.x;
    if (i < n) out[i] = 0.0f;
    if (blockIdx.x == 0) {
        if (threadIdx.x < NEXP) g_cnt[threadIdx.x] = 0;
        if (threadIdx.x == 0) g_zsum = 0.0f;
    }
}

// ---------------- router ----------------
__global__ void k_router(const float* __restrict__ x,
                         const float* __restrict__ gw,
                         const float* __restrict__ bias) {
    const int t = blockIdx.x;
    __shared__ float s_logits[NEXP];
    const int warp = threadIdx.x >> 5;
    const int lane = threadIdx.x & 31;
    const float* xr = x + (size_t)t * DDIM;
    const float* w = gw + (size_t)warp * DDIM;
    float s = 0.0f;
    for (int d = lane; d < DDIM; d += 32) s = fmaf(xr[d], w[d], s);
    #pragma unroll
    for (int o = 16; o; o >>= 1) s += __shfl_xor_sync(0xffffffffu, s, o);
    if (lane == 0) s_logits[warp] = s;
    __syncthreads();
    if (threadIdx.x == 0) {
        float l[NEXP];
        #pragma unroll
        for (int e = 0; e < NEXP; e++) l[e] = s_logits[e];
        int i0 = 0, i1 = -1;
        float b0 = -1e30f, b1 = -1e30f;
        #pragma unroll
        for (int e = 0; e < NEXP; e++) {
            float v = l[e] + bias[e];
            if (v > b0) { b1 = b0; i1 = i0; b0 = v; i0 = e; }
            else if (v > b1) { b1 = v; i1 = e; }
        }
        float l0 = l[i0], l1 = l[i1];
        float m = fmaxf(l0, l1);
        float e0 = expf(l0 - m), e1 = expf(l1 - m);
        float inv = 1.0f / (e0 + e1);
        float w0 = e0 * inv, w1 = e1 * inv;
        float mx = l[0];
        #pragma unroll
        for (int e = 1; e < NEXP; e++) mx = fmaxf(mx, l[e]);
        float se = 0.0f;
        #pragma unroll
        for (int e = 0; e < NEXP; e++) se += expf(l[e] - mx);
        float lse = mx + logf(se);
        atomicAdd(&g_zsum, lse * lse);
        int p0 = atomicAdd(&g_cnt[i0], 1);
        g_tok[i0][p0] = t; g_wt[i0][p0] = w0;
        int p1 = atomicAdd(&g_cnt[i1], 1);
        g_tok[i1][p1] = t; g_wt[i1][p1] = w1;
    }
}

// ---------------- phase 1: act = silu(x Wg) * (x Wu) ----------------
// tile 64(M) x 128(N) x 16(K), 256 threads, 4x8 microtile with f32x2 FMA
__global__ __launch_bounds__(256, 2)
void k_gu(const float* __restrict__ x,
          const float* __restrict__ w_gate,
          const float* __restrict__ w_up) {
    const int e = blockIdx.z;
    const int cnt = g_cnt[e];
    const int m0 = blockIdx.y * 64;
    if (m0 >= cnt) return;
    const int n0 = blockIdx.x * 128;

    __shared__ float sx[16][68];     // padded to cut STS conflicts; row = k
    __shared__ float sg[16][128];
    __shared__ float su[16][128];

    const int tid = threadIdx.x;
    const int tx = tid & 15;
    const int ty = tid >> 4;
    // A load: [64 rows][16 k], one float4/thread
    const int lrow = tid >> 2;
    const int lcol = (tid & 3) << 2;
    const int slot = m0 + lrow;
    const bool avalid = slot < cnt;
    const int tok = avalid ? g_tok[e][slot] : 0;
    const float* xrow = x + (size_t)tok * DDIM;
    // B load: [16 k][128 n], two float4/thread (rows brow, brow+8)
    const int brow = tid >> 5;
    const int bcol = (tid & 31) << 2;
    const float* wg = w_gate + (size_t)e * DDIM * HDIM + n0 + bcol;
    const float* wu = w_up   + (size_t)e * DDIM * HDIM + n0 + bcol;

    u64 accg[4][4] = {};
    u64 accu[4][4] = {};

    float4 pa, pg0, pg1, pu0, pu1;
    pa = avalid ? *(const float4*)(xrow + lcol) : make_float4(0.f,0.f,0.f,0.f);
    pg0 = *(const float4*)(wg + (size_t)brow * HDIM);
    pg1 = *(const float4*)(wg + (size_t)(brow + 8) * HDIM);
    pu0 = *(const float4*)(wu + (size_t)brow * HDIM);
    pu1 = *(const float4*)(wu + (size_t)(brow + 8) * HDIM);

    for (int d0 = 0; d0 < DDIM; d0 += 16) {
        sx[lcol + 0][lrow] = pa.x;
        sx[lcol + 1][lrow] = pa.y;
        sx[lcol + 2][lrow] = pa.z;
        sx[lcol + 3][lrow] = pa.w;
        *(float4*)&sg[brow][bcol]     = pg0;
        *(float4*)&sg[brow + 8][bcol] = pg1;
        *(float4*)&su[brow][bcol]     = pu0;
        *(float4*)&su[brow + 8][bcol] = pu1;
        __syncthreads();

        const int dn = d0 + 16;
        if (dn < DDIM) {
            pa = avalid ? *(const float4*)(xrow + dn + lcol) : make_float4(0.f,0.f,0.f,0.f);
            pg0 = *(const float4*)(wg + (size_t)(dn + brow) * HDIM);
            pg1 = *(const float4*)(wg + (size_t)(dn + brow + 8) * HDIM);
            pu0 = *(const float4*)(wu + (size_t)(dn + brow) * HDIM);
            pu1 = *(const float4*)(wu + (size_t)(dn + brow + 8) * HDIM);
        }

        #pragma unroll
        for (int kk = 0; kk < 16; kk++) {
            float4 av = *(const float4*)&sx[kk][ty << 2];
            float4 g0 = *(const float4*)&sg[kk][tx << 2];
            float4 g1 = *(const float4*)&sg[kk][64 + (tx << 2)];
            float4 u0 = *(const float4*)&su[kk][tx << 2];
            float4 u1 = *(const float4*)&su[kk][64 + (tx << 2)];
            u64 a[4] = {dup2(av.x), dup2(av.y), dup2(av.z), dup2(av.w)};
            u64 bg[4] = {pack2(g0.x, g0.y), pack2(g0.z, g0.w),
                         pack2(g1.x, g1.y), pack2(g1.z, g1.w)};
            u64 bu[4] = {pack2(u0.x, u0.y), pack2(u0.z, u0.w),
                         pack2(u1.x, u1.y), pack2(u1.z, u1.w)};
            #pragma unroll
            for (int i = 0; i < 4; i++) {
                #pragma unroll
                for (int j = 0; j < 4; j++) {
                    fma2(accg[i][j], a[i], bg[j]);
                    fma2(accu[i][j], a[i], bu[j]);
                }
            }
        }
        __syncthreads();
    }

    #pragma unroll
    for (int i = 0; i < 4; i++) {
        const int s2 = m0 + (ty << 2) + i;
        if (s2 < cnt) {
            float* dst = g_act + ((size_t)e * T_TOKENS + s2) * HDIM + n0;
            float g0,g1,g2,g3,uu0,uu1,uu2,uu3;
            // half 0: cols tx*4 .. +3
            unpack2(accg[i][0], g0, g1); unpack2(accg[i][1], g2, g3);
            unpack2(accu[i][0], uu0, uu1); unpack2(accu[i][1], uu2, uu3);
            float4 v;
            v.x = (g0 / (1.0f + __expf(-g0))) * uu0;
            v.y = (g1 / (1.0f + __expf(-g1))) * uu1;
            v.z = (g2 / (1.0f + __expf(-g2))) * uu2;
            v.w = (g3 / (1.0f + __expf(-g3))) * uu3;
            *(float4*)(dst + (tx << 2)) = v;
            // half 1: cols 64 + tx*4 .. +3
            unpack2(accg[i][2], g0, g1); unpack2(accg[i][3], g2, g3);
            unpack2(accu[i][2], uu0, uu1); unpack2(accu[i][3], uu2, uu3);
            v.x = (g0 / (1.0f + __expf(-g0))) * uu0;
            v.y = (g1 / (1.0f + __expf(-g1))) * uu1;
            v.z = (g2 / (1.0f + __expf(-g2))) * uu2;
            v.w = (g3 / (1.0f + __expf(-g3))) * uu3;
            *(float4*)(dst + 64 + (tx << 2)) = v;
        }
    }
}

// ---------------- phase 2: out += weight * (act Wd) ----------------
// tile 64(M) x 128(N over D) x 16(K), 4x8 microtile with f32x2 FMA
__global__ __launch_bounds__(256, 2)
void k_down(const float* __restrict__ w_down, float* __restrict__ out) {
    const int e = blockIdx.z;
    const int cnt = g_cnt[e];
    const int m0 = blockIdx.y * 64;
    if (m0 >= cnt) return;
    const int n0 = blockIdx.x * 128;   // over D: 6 tiles

    __shared__ float sa[16][68];
    __shared__ float sb[16][128];

    const int tid = threadIdx.x;
    const int tx = tid & 15;
    const int ty = tid >> 4;
    const int lrow = tid >> 2;
    const int lcol = (tid & 3) << 2;
    const int slot = m0 + lrow;
    const bool avalid = slot < cnt;
    const float* arow = g_act + ((size_t)e * T_TOKENS + (avalid ? slot : 0)) * HDIM;
    const int brow = tid >> 5;
    const int bcol = (tid & 31) << 2;
    const float* wd = w_down + (size_t)e * HDIM * DDIM + n0 + bcol;

    u64 acc[4][4] = {};

    float4 pa, pb0, pb1;
    pa = avalid ? *(const float4*)(arow + lcol) : make_float4(0.f,0.f,0.f,0.f);
    pb0 = *(const float4*)(wd + (size_t)brow * DDIM);
    pb1 = *(const float4*)(wd + (size_t)(brow + 8) * DDIM);

    for (int h0 = 0; h0 < HDIM; h0 += 16) {
        sa[lcol + 0][lrow] = pa.x;
        sa[lcol + 1][lrow] = pa.y;
        sa[lcol + 2][lrow] = pa.z;
        sa[lcol + 3][lrow] = pa.w;
        *(float4*)&sb[brow][bcol]     = pb0;
        *(float4*)&sb[brow + 8][bcol] = pb1;
        __syncthreads();

        const int hn = h0 + 16;
        if (hn < HDIM) {
            pa = avalid ? *(const float4*)(arow + hn + lcol) : make_float4(0.f,0.f,0.f,0.f);
            pb0 = *(const float4*)(wd + (size_t)(hn + brow) * DDIM);
            pb1 = *(const float4*)(wd + (size_t)(hn + brow + 8) * DDIM);
        }

        #pragma unroll
        for (int kk = 0; kk < 16; kk++) {
            float4 av = *(const float4*)&sa[kk][ty << 2];
            float4 b0 = *(const float4*)&sb[kk][tx << 2];
            float4 b1 = *(const float4*)&sb[kk][64 + (tx << 2)];
            u64 a[4] = {dup2(av.x), dup2(av.y), dup2(av.z), dup2(av.w)};
            u64 bb[4] = {pack2(b0.x, b0.y), pack2(b0.z, b0.w),
                         pack2(b1.x, b1.y), pack2(b1.z, b1.w)};
            #pragma unroll
            for (int i = 0; i < 4; i++)
                #pragma unroll
                for (int j = 0; j < 4; j++)
                    fma2(acc[i][j], a[i], bb[j]);
        }
        __syncthreads();
    }

    #pragma unroll
    for (int i = 0; i < 4; i++) {
        const int s2 = m0 + (ty << 2) + i;
        if (s2 < cnt) {
            const int t = g_tok[e][s2];
            const float w = g_wt[e][s2];
            float* dst = out + (size_t)t * DDIM + n0;
            float v0, v1;
            unpack2(acc[i][0], v0, v1);
            atomicAdd(dst + (tx << 2) + 0, w * v0);
            atomicAdd(dst + (tx << 2) + 1, w * v1);
            unpack2(acc[i][1], v0, v1);
            atomicAdd(dst + (tx << 2) + 2, w * v0);
            atomicAdd(dst + (tx << 2) + 3, w * v1);
            unpack2(acc[i][2], v0, v1);
            atomicAdd(dst + 64 + (tx << 2) + 0, w * v0);
            atomicAdd(dst + 64 + (tx << 2) + 1, w * v1);
            unpack2(acc[i][3], v0, v1);
            atomicAdd(dst + 64 + (tx << 2) + 2, w * v0);
            atomicAdd(dst + 64 + (tx << 2) + 3, w * v1);
        }
    }
}

// ---------------- z-loss finalize ----------------
__global__ void k_zloss(float* __restrict__ zout) {
    zout[0] = Z_COEFF * g_zsum / (float)T_TOKENS;
}

extern "C" void kernel_launch(void* const* d_in, const int* in_sizes, int n_in,
                              void* d_out, int out_size) {
    const float* x           = (const float*)d_in[0];
    const float* gate_w      = (const float*)d_in[1];
    const float* expert_bias = (const float*)d_in[2];
    const float* w_gate      = (const float*)d_in[3];
    const float* w_up        = (const float*)d_in[4];
    const float* w_down      = (const float*)d_in[5];
    float* out = (float*)d_out;

    const int n_main = T_TOKENS * DDIM;

    k_init<<<(out_size + 255) / 256, 256>>>(out, out_size);
    k_router<<<T_TOKENS, 256>>>(x, gate_w, expert_bias);
    k_gu<<<dim3(HDIM / 128, T_TOKENS / 64, NEXP), 256>>>(x, w_gate, w_up);
    k_down<<<dim3(DDIM / 128, T_TOKENS / 64, NEXP), 256>>>(w_down, out);
    if (out_size > n_main) {
        k_zloss<<<1, 1>>>(out + n_main);
    }
}

// round 5
// speedup vs baseline: 2.5563x; 2.2295x over previous
#include <cuda_runtime.h>
#include <cuda_bf16.h>
#include <stdint.h>
#include <math.h>

#define T_TOKENS 4096
#define DDIM 768
#define HDIM 2688
#define NEXP 8
#define Z_COEFF 1e-5f

typedef __nv_bfloat16 bf16;

// ===================== helpers =====================
__device__ __forceinline__ uint32_t smem_u32(const void* p) {
    uint32_t a;
    asm("{ .reg .u64 t; cvta.to.shared.u64 t, %1; cvt.u32.u64 %0, t; }" : "=r"(a) : "l"(p));
    return a;
}
__device__ __forceinline__ void ldsm_x4(uint32_t* r, uint32_t a) {
    asm volatile("ldmatrix.sync.aligned.m8n8.x4.shared.b16 {%0,%1,%2,%3}, [%4];"
        : "=r"(r[0]), "=r"(r[1]), "=r"(r[2]), "=r"(r[3]) : "r"(a));
}
__device__ __forceinline__ void mma_bf16(float* c, const uint32_t* a, const uint32_t* b) {
    asm volatile("mma.sync.aligned.m16n8k16.row.col.f32.bf16.bf16.f32 "
        "{%0,%1,%2,%3}, {%4,%5,%6,%7}, {%8,%9}, {%0,%1,%2,%3};"
        : "+f"(c[0]), "+f"(c[1]), "+f"(c[2]), "+f"(c[3])
        : "r"(a[0]), "r"(a[1]), "r"(a[2]), "r"(a[3]), "r"(b[0]), "r"(b[1]));
}
__device__ __forceinline__ void cp16(uint32_t dst, const void* src, uint32_t sz) {
    asm volatile("cp.async.ca.shared.global [%0], [%1], 16, %2;"
        :: "r"(dst), "l"(src), "r"(sz) : "memory");
}
#define CP_COMMIT() asm volatile("cp.async.commit_group;" ::: "memory")
#define CP_WAIT_1() asm volatile("cp.async.wait_group 1;" ::: "memory")
#define CP_WAIT_0() asm volatile("cp.async.wait_group 0;" ::: "memory")

// ===================== device scratch =====================
__device__ int   g_cnt[NEXP];
__device__ int   g_base[NEXP];
__device__ int   g_tok[NEXP][T_TOKENS];
__device__ float g_wt[NEXP][T_TOKENS];
__device__ float g_zsum;
__device__ bf16  g_xh[(size_t)T_TOKENS * DDIM];
__device__ bf16  g_xl[(size_t)T_TOKENS * DDIM];
// transposed split weights: [E][H][D] for gate/up, [E][D][H] for down
__device__ bf16  g_wgh[(size_t)NEXP * HDIM * DDIM];
__device__ bf16  g_wgl[(size_t)NEXP * HDIM * DDIM];
__device__ bf16  g_wuh[(size_t)NEXP * HDIM * DDIM];
__device__ bf16  g_wul[(size_t)NEXP * HDIM * DDIM];
__device__ bf16  g_wdh[(size_t)NEXP * DDIM * HDIM];
__device__ bf16  g_wdl[(size_t)NEXP * DDIM * HDIM];
// split activations, compact rows (g_base[e] + slot)
__device__ bf16  g_acth[(size_t)2 * T_TOKENS * HDIM];
__device__ bf16  g_actl[(size_t)2 * T_TOKENS * HDIM];

// ===================== init =====================
__global__ void k_init(float* __restrict__ out, int n) {
    int i = blockIdx.x * blockDim.x + threadIdx.x;
    if (i < n) out[i] = 0.0f;
    if (blockIdx.x == 0) {
        if (threadIdx.x < NEXP) g_cnt[threadIdx.x] = 0;
        if (threadIdx.x == 0) g_zsum = 0.0f;
    }
}

// ===================== router =====================
__global__ void k_router(const float* __restrict__ x,
                         const float* __restrict__ gw,
                         const float* __restrict__ bias) {
    const int t = blockIdx.x;
    __shared__ float s_logits[NEXP];
    const int warp = threadIdx.x >> 5;
    const int lane = threadIdx.x & 31;
    const float* xr = x + (size_t)t * DDIM;
    const float* w = gw + (size_t)warp * DDIM;
    float s = 0.0f;
    for (int d = lane; d < DDIM; d += 32) s = fmaf(xr[d], w[d], s);
    #pragma unroll
    for (int o = 16; o; o >>= 1) s += __shfl_xor_sync(0xffffffffu, s, o);
    if (lane == 0) s_logits[warp] = s;
    __syncthreads();
    if (threadIdx.x == 0) {
        float l[NEXP];
        #pragma unroll
        for (int e = 0; e < NEXP; e++) l[e] = s_logits[e];
        int i0 = 0, i1 = -1;
        float b0 = -1e30f, b1 = -1e30f;
        #pragma unroll
        for (int e = 0; e < NEXP; e++) {
            float v = l[e] + bias[e];
            if (v > b0) { b1 = b0; i1 = i0; b0 = v; i0 = e; }
            else if (v > b1) { b1 = v; i1 = e; }
        }
        float l0 = l[i0], l1 = l[i1];
        float m = fmaxf(l0, l1);
        float e0 = expf(l0 - m), e1 = expf(l1 - m);
        float inv = 1.0f / (e0 + e1);
        float mx = l[0];
        #pragma unroll
        for (int e = 1; e < NEXP; e++) mx = fmaxf(mx, l[e]);
        float se = 0.0f;
        #pragma unroll
        for (int e = 0; e < NEXP; e++) se += expf(l[e] - mx);
        float lse = mx + logf(se);
        atomicAdd(&g_zsum, lse * lse);
        int p0 = atomicAdd(&g_cnt[i0], 1);
        g_tok[i0][p0] = t; g_wt[i0][p0] = e0 * inv;
        int p1 = atomicAdd(&g_cnt[i1], 1);
        g_tok[i1][p1] = t; g_wt[i1][p1] = e1 * inv;
    }
}

__global__ void k_offsets() {
    if (threadIdx.x == 0) {
        int s = 0;
        for (int e = 0; e < NEXP; e++) { g_base[e] = s; s += g_cnt[e]; }
    }
}

// ===================== precision splits =====================
__device__ __forceinline__ void split_bf16(float v, bf16& h, bf16& l) {
    h = __float2bfloat16(v);
    l = __float2bfloat16(v - __bfloat162float(h));
}

__global__ void k_split_x(const float* __restrict__ x) {
    int i = blockIdx.x * blockDim.x + threadIdx.x;
    if (i < T_TOKENS * DDIM) {
        bf16 h, l; split_bf16(x[i], h, l);
        g_xh[i] = h; g_xl[i] = l;
    }
}

// transpose+split w_gate / w_up : [E][D][H] -> [E][H][D]
__global__ void k_split_wT(const float* __restrict__ w_gate,
                           const float* __restrict__ w_up) {
    __shared__ float t[32][33];
    const int e = blockIdx.z >> 1;
    const bool up = blockIdx.z & 1;
    const float* src = (up ? w_up : w_gate) + (size_t)e * DDIM * HDIM;
    bf16* oh = (up ? g_wuh : g_wgh) + (size_t)e * HDIM * DDIM;
    bf16* ol = (up ? g_wul : g_wgl) + (size_t)e * HDIM * DDIM;
    const int h0 = blockIdx.x * 32, d0 = blockIdx.y * 32;
    const int tx = threadIdx.x & 31, ty = threadIdx.x >> 5;
    #pragma unroll
    for (int i = 0; i < 32; i += 8)
        t[ty + i][tx] = src[(size_t)(d0 + ty + i) * HDIM + h0 + tx];
    __syncthreads();
    #pragma unroll
    for (int i = 0; i < 32; i += 8) {
        float v = t[tx][ty + i];
        bf16 h, l; split_bf16(v, h, l);
        size_t o = (size_t)(h0 + ty + i) * DDIM + d0 + tx;
        oh[o] = h; ol[o] = l;
    }
}

// transpose+split w_down : [E][H][D] -> [E][D][H]
__global__ void k_split_wd(const float* __restrict__ w_down) {
    __shared__ float t[32][33];
    const int e = blockIdx.z;
    const float* src = w_down + (size_t)e * HDIM * DDIM;
    bf16* oh = g_wdh + (size_t)e * DDIM * HDIM;
    bf16* ol = g_wdl + (size_t)e * DDIM * HDIM;
    const int r0 = blockIdx.y * 32;   // over H
    const int c0 = blockIdx.x * 32;   // over D
    const int tx = threadIdx.x & 31, ty = threadIdx.x >> 5;
    #pragma unroll
    for (int i = 0; i < 32; i += 8)
        t[ty + i][tx] = src[(size_t)(r0 + ty + i) * DDIM + c0 + tx];
    __syncthreads();
    #pragma unroll
    for (int i = 0; i < 32; i += 8) {
        float v = t[tx][ty + i];
        bf16 h, l; split_bf16(v, h, l);
        size_t o = (size_t)(c0 + ty + i) * HDIM + r0 + tx;
        oh[o] = h; ol[o] = l;
    }
}

// ===================== GEMM tiling constants =====================
#define PITCH 80                      // 64B data + 16B pad; conflict-free ldmatrix
#define A_TILE (128 * PITCH)          // 10240 B
#define B_TILE (64 * PITCH)           // 5120 B
#define STG1 (2 * A_TILE + 4 * B_TILE)   // 40960
#define STG2 (2 * A_TILE + 2 * B_TILE)   // 30720
#define NCH1 (DDIM / 32)              // 24
#define NCH2 (HDIM / 32)              // 84

// ===================== phase 1: gate+up GEMM (HMMA, split-3) =====================
__global__ __launch_bounds__(256, 2)
void k_gu_mma() {
    const int e = blockIdx.z;
    const int cnt = g_cnt[e];
    const int m0 = blockIdx.y * 128;
    if (m0 >= cnt) return;
    const int n0 = blockIdx.x * 64;

    extern __shared__ char sm[];
    __shared__ int s_tok[128];
    const int tid = threadIdx.x, lane = tid & 31, wid = tid >> 5;
    const int wm = wid >> 2, wn = wid & 3;
    if (tid < 128) { int s = m0 + tid; s_tok[tid] = (s < cnt) ? g_tok[e][s] : -1; }
    __syncthreads();
    const uint32_t smb = smem_u32(sm);

    const size_t woff = (size_t)(e * HDIM + n0) * DDIM;
    const bf16* wb0 = g_wgh + woff;
    const bf16* wb1 = g_wgl + woff;
    const bf16* wb2 = g_wuh + woff;
    const bf16* wb3 = g_wul + woff;

    auto issue = [&](int stage, int d0) {
        uint32_t sb = smb + stage * STG1;
        #pragma unroll
        for (int i = 0; i < 4; i++) {
            int idx = tid + i * 256;
            int tile = idx >> 9, rem = idx & 511, row = rem >> 2, seg = rem & 3;
            int tok = s_tok[row];
            const bf16* src = (tile ? g_xl : g_xh)
                + (size_t)(tok < 0 ? 0 : tok) * DDIM + d0 + seg * 8;
            cp16(sb + tile * A_TILE + row * PITCH + seg * 16, src, tok >= 0 ? 16u : 0u);
        }
        #pragma unroll
        for (int i = 0; i < 4; i++) {
            int idx = tid + i * 256;
            int mat = idx >> 8, rem = idx & 255, row = rem >> 2, seg = rem & 3;
            const bf16* src = (mat == 0 ? wb0 : mat == 1 ? wb1 : mat == 2 ? wb2 : wb3)
                + (size_t)row * DDIM + d0 + seg * 8;
            cp16(sb + 2 * A_TILE + mat * B_TILE + row * PITCH + seg * 16, src, 16u);
        }
        CP_COMMIT();
    };

    float accg[4][2][4] = {};
    float accu[4][2][4] = {};

    issue(0, 0);
    const uint32_t aBase = (uint32_t)((wm * 64 + (lane & 15)) * PITCH + ((lane >> 4) * 16));
    const uint32_t bBase = (uint32_t)((wn * 16 + (lane & 7) + ((lane & 16) ? 8 : 0)) * PITCH
                                      + (((lane >> 3) & 1) * 16));

    for (int c = 0; c < NCH1; c++) {
        if (c + 1 < NCH1) { issue((c + 1) & 1, (c + 1) * 32); CP_WAIT_1(); }
        else               { CP_WAIT_0(); }
        __syncthreads();
        const uint32_t sA = smb + (c & 1) * STG1;
        const uint32_t sB = sA + 2 * A_TILE;
        #pragma unroll
        for (int ks = 0; ks < 2; ks++) {
            const uint32_t kc = ks * 32;
            uint32_t b0[4], b1[4], b2[4], b3[4];
            ldsm_x4(b0, sB + 0 * B_TILE + bBase + kc);
            ldsm_x4(b1, sB + 1 * B_TILE + bBase + kc);
            ldsm_x4(b2, sB + 2 * B_TILE + bBase + kc);
            ldsm_x4(b3, sB + 3 * B_TILE + bBase + kc);
            #pragma unroll
            for (int mt = 0; mt < 4; mt++) {
                uint32_t ah[4], al[4];
                const uint32_t ao = aBase + mt * 16 * PITCH + kc;
                ldsm_x4(ah, sA + ao);
                ldsm_x4(al, sA + A_TILE + ao);
                mma_bf16(accg[mt][0], ah, b0 + 0); mma_bf16(accg[mt][1], ah, b0 + 2);
                mma_bf16(accg[mt][0], ah, b1 + 0); mma_bf16(accg[mt][1], ah, b1 + 2);
                mma_bf16(accg[mt][0], al, b0 + 0); mma_bf16(accg[mt][1], al, b0 + 2);
                mma_bf16(accu[mt][0], ah, b2 + 0); mma_bf16(accu[mt][1], ah, b2 + 2);
                mma_bf16(accu[mt][0], ah, b3 + 0); mma_bf16(accu[mt][1], ah, b3 + 2);
                mma_bf16(accu[mt][0], al, b2 + 0); mma_bf16(accu[mt][1], al, b2 + 2);
            }
        }
        __syncthreads();
    }

    // epilogue: act = silu(g) * u, split to bf16 hi/lo
    const int rw = lane >> 2;
    const int cw = (lane & 3) * 2;
    #pragma unroll
    for (int mt = 0; mt < 4; mt++) {
        #pragma unroll
        for (int half = 0; half < 2; half++) {
            const int slot = m0 + wm * 64 + mt * 16 + rw + half * 8;
            if (slot < cnt) {
                const size_t rowoff = (size_t)(g_base[e] + slot) * HDIM;
                #pragma unroll
                for (int nt = 0; nt < 2; nt++) {
                    float g0 = accg[mt][nt][half * 2 + 0], g1 = accg[mt][nt][half * 2 + 1];
                    float u0 = accu[mt][nt][half * 2 + 0], u1 = accu[mt][nt][half * 2 + 1];
                    float v0 = (g0 / (1.0f + __expf(-g0))) * u0;
                    float v1 = (g1 / (1.0f + __expf(-g1))) * u1;
                    const int col = n0 + wn * 16 + nt * 8 + cw;
                    bf16 h0, l0, h1, l1;
                    split_bf16(v0, h0, l0);
                    split_bf16(v1, h1, l1);
                    __nv_bfloat162 ph; ph.x = h0; ph.y = h1;
                    __nv_bfloat162 pl; pl.x = l0; pl.y = l1;
                    *(__nv_bfloat162*)(g_acth + rowoff + col) = ph;
                    *(__nv_bfloat162*)(g_actl + rowoff + col) = pl;
                }
            }
        }
    }
}

// ===================== phase 2: down GEMM + weighted scatter =====================
__global__ __launch_bounds__(256, 2)
void k_down_mma(float* __restrict__ out) {
    const int e = blockIdx.z;
    const int cnt = g_cnt[e];
    const int m0 = blockIdx.y * 128;
    if (m0 >= cnt) return;
    const int n0 = blockIdx.x * 64;   // over D: 12 tiles

    extern __shared__ char sm[];
    __shared__ int   s_tok[128];
    __shared__ float s_wt[128];
    const int tid = threadIdx.x, lane = tid & 31, wid = tid >> 5;
    const int wm = wid >> 2, wn = wid & 3;
    if (tid < 128) {
        int s = m0 + tid;
        s_tok[tid] = (s < cnt) ? g_tok[e][s] : -1;
        s_wt[tid]  = (s < cnt) ? g_wt[e][s] : 0.0f;
    }
    __syncthreads();
    const uint32_t smb = smem_u32(sm);

    const size_t woff = (size_t)(e * DDIM + n0) * HDIM;
    const bf16* wb0 = g_wdh + woff;
    const bf16* wb1 = g_wdl + woff;
    const size_t abase = (size_t)(g_base[e] + m0) * HDIM;

    auto issue = [&](int stage, int h0) {
        uint32_t sb = smb + stage * STG2;
        #pragma unroll
        for (int i = 0; i < 4; i++) {
            int idx = tid + i * 256;
            int tile = idx >> 9, rem = idx & 511, row = rem >> 2, seg = rem & 3;
            const bool ok = (m0 + row) < cnt;
            const bf16* src = (tile ? g_actl : g_acth)
                + abase + (size_t)(ok ? row : 0) * HDIM + h0 + seg * 8;
            cp16(sb + tile * A_TILE + row * PITCH + seg * 16, src, ok ? 16u : 0u);
        }
        #pragma unroll
        for (int i = 0; i < 2; i++) {
            int idx = tid + i * 256;
            int mat = idx >> 8, rem = idx & 255, row = rem >> 2, seg = rem & 3;
            const bf16* src = (mat == 0 ? wb0 : wb1) + (size_t)row * HDIM + h0 + seg * 8;
            cp16(sb + 2 * A_TILE + mat * B_TILE + row * PITCH + seg * 16, src, 16u);
        }
        CP_COMMIT();
    };

    float acc[4][2][4] = {};

    issue(0, 0);
    const uint32_t aBase = (uint32_t)((wm * 64 + (lane & 15)) * PITCH + ((lane >> 4) * 16));
    const uint32_t bBase = (uint32_t)((wn * 16 + (lane & 7) + ((lane & 16) ? 8 : 0)) * PITCH
                                      + (((lane >> 3) & 1) * 16));

    for (int c = 0; c < NCH2; c++) {
        if (c + 1 < NCH2) { issue((c + 1) & 1, (c + 1) * 32); CP_WAIT_1(); }
        else               { CP_WAIT_0(); }
        __syncthreads();
        const uint32_t sA = smb + (c & 1) * STG2;
        const uint32_t sB = sA + 2 * A_TILE;
        #pragma unroll
        for (int ks = 0; ks < 2; ks++) {
            const uint32_t kc = ks * 32;
            uint32_t b0[4], b1[4];
            ldsm_x4(b0, sB + 0 * B_TILE + bBase + kc);
            ldsm_x4(b1, sB + 1 * B_TILE + bBase + kc);
            #pragma unroll
            for (int mt = 0; mt < 4; mt++) {
                uint32_t ah[4], al[4];
                const uint32_t ao = aBase + mt * 16 * PITCH + kc;
                ldsm_x4(ah, sA + ao);
                ldsm_x4(al, sA + A_TILE + ao);
                mma_bf16(acc[mt][0], ah, b0 + 0); mma_bf16(acc[mt][1], ah, b0 + 2);
                mma_bf16(acc[mt][0], ah, b1 + 0); mma_bf16(acc[mt][1], ah, b1 + 2);
                mma_bf16(acc[mt][0], al, b0 + 0); mma_bf16(acc[mt][1], al, b0 + 2);
            }
        }
        __syncthreads();
    }

    // epilogue: out[token] += weight * val (atomic)
    const int rw = lane >> 2;
    const int cw = (lane & 3) * 2;
    #pragma unroll
    for (int mt = 0; mt < 4; mt++) {
        #pragma unroll
        for (int half = 0; half < 2; half++) {
            const int lrow = wm * 64 + mt * 16 + rw + half * 8;
            const int slot = m0 + lrow;
            if (slot < cnt) {
                const int t = s_tok[lrow];
                const float w = s_wt[lrow];
                float* dst = out + (size_t)t * DDIM;
                #pragma unroll
                for (int nt = 0; nt < 2; nt++) {
                    const int col = n0 + wn * 16 + nt * 8 + cw;
                    atomicAdd(dst + col,     w * acc[mt][nt][half * 2 + 0]);
                    atomicAdd(dst + col + 1, w * acc[mt][nt][half * 2 + 1]);
                }
            }
        }
    }
}

// ===================== z-loss =====================
__global__ void k_zloss(float* __restrict__ zout) {
    zout[0] = Z_COEFF * g_zsum / (float)T_TOKENS;
}

// ===================== launch =====================
extern "C" void kernel_launch(void* const* d_in, const int* in_sizes, int n_in,
                              void* d_out, int out_size) {
    const float* x           = (const float*)d_in[0];
    const float* gate_w      = (const float*)d_in[1];
    const float* expert_bias = (const float*)d_in[2];
    const float* w_gate      = (const float*)d_in[3];
    const float* w_up        = (const float*)d_in[4];
    const float* w_down      = (const float*)d_in[5];
    float* out = (float*)d_out;

    static int attr_done = 0;
    if (!attr_done) {
        cudaFuncSetAttribute(k_gu_mma,   cudaFuncAttributeMaxDynamicSharedMemorySize, 2 * STG1);
        cudaFuncSetAttribute(k_down_mma, cudaFuncAttributeMaxDynamicSharedMemorySize, 2 * STG2);
        attr_done = 1;
    }

    const int n_main = T_TOKENS * DDIM;

    k_init<<<(out_size + 255) / 256, 256>>>(out, out_size);
    k_router<<<T_TOKENS, 256>>>(x, gate_w, expert_bias);
    k_offsets<<<1, 32>>>();
    k_split_x<<<(T_TOKENS * DDIM + 255) / 256, 256>>>(x);
    k_split_wT<<<dim3(HDIM / 32, DDIM / 32, NEXP * 2), 256>>>(w_gate, w_up);
    k_split_wd<<<dim3(DDIM / 32, HDIM / 32, NEXP), 256>>>(w_down);
    k_gu_mma<<<dim3(HDIM / 64, T_TOKENS / 128, NEXP), 256, 2 * STG1>>>();
    k_down_mma<<<dim3(DDIM / 64, T_TOKENS / 128, NEXP), 256, 2 * STG2>>>(out);
    if (out_size > n_main) k_zloss<<<1, 1>>>(out + n_main);
}